// round 14
// baseline (speedup 1.0000x reference)
#include <cuda_runtime.h>

// Hamilton product of quaternions packed in the last dim (w, x, y, z).
// Shapes: q1, q2: (32, 4096, 64, 4) fp32 -> 8,388,608 quaternions.
//
// HBM-bound 2R+1W stream (~403 MB, zero reuse), pinned at 83-85% of HBM
// spec in every sweep variant. Harness graph-replay timing favors the
// QPT=1 shape (one coalesced LDG.128 pair per thread, no front-batched
// MLP bursts): bench mean 60.5us vs 62.4us for all ILP variants.
// R14: last untested knob in the winning family — TPB=512 (halves CTA
// count; per-thread access pattern identical).

#define TPB 512

__global__ void __launch_bounds__(TPB) hamilton_kernel(
    const float4* __restrict__ q1,
    const float4* __restrict__ q2,
    float4* __restrict__ out,
    int n_quat)
{
    int i = blockIdx.x * TPB + threadIdx.x;
    if (i >= n_quat) return;

    float4 a = q1[i];
    float4 b = q2[i];

    // a = (w1, x1, y1, z1), b = (w2, x2, y2, z2)
    float4 r;
    r.x = a.x * b.x - a.y * b.y - a.z * b.z - a.w * b.w;  // w
    r.y = a.x * b.y + a.y * b.x + a.z * b.w - a.w * b.z;  // x
    r.z = a.x * b.z - a.y * b.w + a.z * b.x + a.w * b.y;  // y
    r.w = a.x * b.w + a.y * b.z - a.z * b.y + a.w * b.x;  // z

    out[i] = r;
}

extern "C" void kernel_launch(void* const* d_in, const int* in_sizes, int n_in,
                              void* d_out, int out_size) {
    const float4* q1 = (const float4*)d_in[0];
    const float4* q2 = (const float4*)d_in[1];
    float4* out = (float4*)d_out;

    int n_quat = in_sizes[0] / 4;  // 8,388,608

    int blocks = (n_quat + TPB - 1) / TPB;  // 16384
    hamilton_kernel<<<blocks, TPB>>>(q1, q2, out, n_quat);
}